// round 8
// baseline (speedup 1.0000x reference)
#include <cuda_runtime.h>
#include <cuda_fp16.h>
#include <mma.h>
#include <math.h>
#include <stdint.h>

using namespace nvcuda;

#define B_TOK 8192
#define H_DIM 1024
#define N_EXP 8
#define MAX_ROWS 17536   // 137 tiles * 128

// ---------------- scratch (static device memory; no allocations) ----------------
__device__ __half g_x_f16[B_TOK * H_DIM];
__device__ __half g_w_f16[N_EXP * H_DIM * H_DIM];   // [e][k][n] native layout

__device__ int   g_tok_e[B_TOK * 2];
__device__ float g_tok_w[B_TOK * 2];
__device__ int   g_counts[N_EXP];
__device__ int   g_cursor[N_EXP];
__device__ int   g_poff[N_EXP + 1];
__device__ int   g_tileoff[N_EXP + 1];
__device__ int   g_rows_tok[MAX_ROWS];
__device__ float g_roww[MAX_ROWS];      // per-row combine weight (0 for padding)

// ---------------- helpers ----------------
#define CP_ASYNC16(dst, src) \
    asm volatile("cp.async.cg.shared.global [%0], [%1], 16;\n" :: "r"(dst), "l"(src))
#define CP_COMMIT() asm volatile("cp.async.commit_group;\n" ::: "memory")
#define CP_WAIT(n)  asm volatile("cp.async.wait_group %0;\n" :: "n"(n) : "memory")

__device__ __forceinline__ uint32_t smem_u32(const void* p) {
    uint32_t a;
    asm("{ .reg .u64 t; cvta.to.shared.u64 t, %1; cvt.u32.u64 %0, t; }" : "=r"(a) : "l"(p));
    return a;
}

// ---------------- convert (fp32->fp16 x,w) + zero out + init ----------------
__global__ void convert_kernel(const float* __restrict__ x, const float* __restrict__ w,
                               float* __restrict__ out) {
    int gid = blockIdx.x * blockDim.x + threadIdx.x;
    if (gid < N_EXP) { g_counts[gid] = 0; g_cursor[gid] = 0; }
    if (gid < MAX_ROWS) { g_rows_tok[gid] = 0; g_roww[gid] = 0.0f; }

    const int n4 = (B_TOK * H_DIM) / 4;   // 2M float4 per tensor (and out)
    const int stride = gridDim.x * blockDim.x;
    const float4 z4 = make_float4(0.f, 0.f, 0.f, 0.f);
    for (int j = gid; j < n4; j += stride) {
        float4 v = reinterpret_cast<const float4*>(x)[j];
        __half2 p0 = __floats2half2_rn(v.x, v.y);
        __half2 p1 = __floats2half2_rn(v.z, v.w);
        reinterpret_cast<__half2*>(g_x_f16)[2 * j]     = p0;
        reinterpret_cast<__half2*>(g_x_f16)[2 * j + 1] = p1;

        float4 u = reinterpret_cast<const float4*>(w)[j];
        p0 = __floats2half2_rn(u.x, u.y);
        p1 = __floats2half2_rn(u.z, u.w);
        reinterpret_cast<__half2*>(g_w_f16)[2 * j]     = p0;
        reinterpret_cast<__half2*>(g_w_f16)[2 * j + 1] = p1;

        reinterpret_cast<float4*>(out)[j] = z4;
    }
}

// ---------------- gate (R4 exact) ----------------
__global__ void gate_kernel(const float* __restrict__ x, const float* __restrict__ gw) {
    __shared__ float sgw[N_EXP * H_DIM];
    int tid = threadIdx.x;
    for (int i = tid; i < N_EXP * H_DIM; i += blockDim.x) {
        int h = i >> 3, e = i & 7;
        sgw[e * H_DIM + h] = gw[i];
    }
    __syncthreads();
    int warp = tid >> 5, lane = tid & 31;
    int b = blockIdx.x * 8 + warp;
    const float* xr = x + (size_t)b * H_DIM;
    float acc[N_EXP];
#pragma unroll
    for (int e = 0; e < N_EXP; e++) acc[e] = 0.0f;
    for (int i = lane; i < H_DIM; i += 32) {
        float xv = xr[i];
#pragma unroll
        for (int e = 0; e < N_EXP; e++) acc[e] += xv * sgw[e * H_DIM + i];
    }
#pragma unroll
    for (int e = 0; e < N_EXP; e++) {
#pragma unroll
        for (int o = 16; o > 0; o >>= 1)
            acc[e] += __shfl_down_sync(0xffffffffu, acc[e], o);
    }
    if (lane == 0) {
        float b1v = -1e30f; int b1 = 0;
#pragma unroll
        for (int e = 0; e < N_EXP; e++)
            if (acc[e] > b1v) { b1v = acc[e]; b1 = e; }
        float b2v = -1e30f; int b2 = 0;
#pragma unroll
        for (int e = 0; e < N_EXP; e++)
            if (e != b1 && acc[e] > b2v) { b2v = acc[e]; b2 = e; }
        float e2 = expf(b2v - b1v);
        float inv = 1.0f / (1.0f + e2);
        g_tok_e[2 * b]     = b1;
        g_tok_e[2 * b + 1] = b2;
        g_tok_w[2 * b]     = inv;
        g_tok_w[2 * b + 1] = e2 * inv;
        atomicAdd(&g_counts[b1], 1);
        atomicAdd(&g_counts[b2], 1);
    }
}

// ---------------- scatter: prefix + permutation + per-row weights ----------------
__global__ void scatter_kernel() {
    __shared__ int s_poff[N_EXP + 1];
    if (threadIdx.x == 0) {
        int po = 0, to = 0;
        int poff[N_EXP + 1], tilo[N_EXP + 1];
        for (int e = 0; e < N_EXP; e++) {
            poff[e] = po; tilo[e] = to;
            int t = (g_counts[e] + 127) >> 7;
            to += t;
            po += t << 7;
        }
        poff[N_EXP] = po; tilo[N_EXP] = to;
        for (int e = 0; e <= N_EXP; e++) s_poff[e] = poff[e];
        if (blockIdx.x == 0) {
            for (int e = 0; e <= N_EXP; e++) { g_poff[e] = poff[e]; g_tileoff[e] = tilo[e]; }
        }
    }
    __syncthreads();
    int b = blockIdx.x * blockDim.x + threadIdx.x;
    if (b >= B_TOK) return;
#pragma unroll
    for (int j = 0; j < 2; j++) {
        int e = g_tok_e[2 * b + j];
        int p = s_poff[e] + atomicAdd(&g_cursor[e], 1);
        g_rows_tok[p] = b;
        g_roww[p] = g_tok_w[2 * b + j];
    }
}

// ---------------- grouped GEMM + fused weighted scatter-add epilogue ----------------
#define N_STAGE 3
#define SA_LD 72
#define SB_LD 136
#define SA_ST (128 * SA_LD)
#define SB_ST (64 * SB_LD)
#define SB_BASE (N_STAGE * SA_ST)
#define TOK_BASE_B ((N_STAGE * SA_ST + N_STAGE * SB_ST) * 2)
#define W_BASE_B (TOK_BASE_B + 512)
#define SMEM_TOTAL (W_BASE_B + 512)
#define SF_LD 132   // f32 staging row pitch (floats)

__global__ __launch_bounds__(256, 2) void gemm_f16_kernel(float* __restrict__ out) {
    int mt = blockIdx.x;
    if (mt >= g_tileoff[N_EXP]) return;
    int e = 0;
    while (mt >= g_tileoff[e + 1]) e++;
    int row0 = g_poff[e] + ((mt - g_tileoff[e]) << 7);
    int n0 = blockIdx.y << 7;

    extern __shared__ char smem[];
    __half* sA = reinterpret_cast<__half*>(smem);
    __half* sB = reinterpret_cast<__half*>(smem) + SB_BASE;
    int* s_tok = reinterpret_cast<int*>(smem + TOK_BASE_B);
    float* s_w = reinterpret_cast<float*>(smem + W_BASE_B);
    uint32_t sbase = smem_u32(smem);

    int tid = threadIdx.x;
    if (tid < 128) {
        s_tok[tid] = g_rows_tok[row0 + tid];
        s_w[tid]   = g_roww[row0 + tid];
    }
    __syncthreads();

    const __half* wbase = g_w_f16 + (size_t)e * H_DIM * H_DIM + n0;

    auto do_load = [&](int st, int k0) {
        uint32_t aoff = sbase + (uint32_t)(st * SA_ST * 2);
        uint32_t boff = sbase + (uint32_t)((SB_BASE + st * SB_ST) * 2);
#pragma unroll
        for (int ii = 0; ii < 4; ii++) {
            int idx = tid + ii * 256;
            int ra = idx >> 3, ca = idx & 7;
            const char* asrc = (const char*)(g_x_f16 + (size_t)s_tok[ra] * H_DIM + k0) + ca * 16;
            CP_ASYNC16(aoff + (uint32_t)(ra * SA_LD + ca * 8) * 2, asrc);
            int rb = idx >> 4, cb = idx & 15;
            const char* bsrc = (const char*)(wbase + (size_t)(k0 + rb) * H_DIM) + cb * 16;
            CP_ASYNC16(boff + (uint32_t)(rb * SB_LD + cb * 8) * 2, bsrc);
        }
        CP_COMMIT();
    };

    int wid = tid >> 5;
    int wm = wid & 3;
    int wn = wid >> 2;

    wmma::fragment<wmma::accumulator, 16, 16, 16, float> acc[2][4];
#pragma unroll
    for (int f = 0; f < 2; f++)
#pragma unroll
        for (int j = 0; j < 4; j++) wmma::fill_fragment(acc[f][j], 0.0f);

    do_load(0, 0);
    do_load(1, 64);

    for (int it = 0; it < 16; it++) {
        int st = it % N_STAGE;
        if (it == 15) { CP_WAIT(0); } else { CP_WAIT(1); }
        __syncthreads();
        if (it + 2 < 16) do_load((it + 2) % N_STAGE, (it + 2) << 6);

        const __half* A0 = sA + st * SA_ST + (wm * 32) * SA_LD;
        const __half* B0 = sB + st * SB_ST + wn * 64;
#pragma unroll
        for (int ks = 0; ks < 4; ks++) {
            wmma::fragment<wmma::matrix_a, 16, 16, 16, __half, wmma::row_major> af[2];
            wmma::load_matrix_sync(af[0], A0 + ks * 16, SA_LD);
            wmma::load_matrix_sync(af[1], A0 + 16 * SA_LD + ks * 16, SA_LD);
#pragma unroll
            for (int j = 0; j < 4; j++) {
                wmma::fragment<wmma::matrix_b, 16, 16, 16, __half, wmma::row_major> bf;
                wmma::load_matrix_sync(bf, B0 + (ks * 16) * SB_LD + j * 16, SB_LD);
                wmma::mma_sync(acc[0][j], af[0], bf, acc[0][j]);
                wmma::mma_sync(acc[1][j], af[1], bf, acc[1][j]);
            }
        }
    }

    // ---- epilogue: stage f32 accs into (dead) smem, then weighted atomicAdd to out ----
    __syncthreads();
    float* sF = reinterpret_cast<float*>(smem);   // [128][SF_LD] floats = 67.6 KB
#pragma unroll
    for (int f = 0; f < 2; f++)
#pragma unroll
        for (int j = 0; j < 4; j++)
            wmma::store_matrix_sync(sF + (size_t)(wm * 32 + f * 16) * SF_LD + wn * 64 + j * 16,
                                    acc[f][j], SF_LD, wmma::mem_row_major);
    __syncthreads();
    // 128 rows x 128 cols: 16 threads/row, 8 cols/thread
#pragma unroll
    for (int q = tid; q < 2048; q += 256) {
        int r = q >> 4;
        int c = (q & 15) << 3;
        float w = s_w[r];
        if (w == 0.0f) continue;    // padding row
        int tok = s_tok[r];
        const float* src = sF + (size_t)r * SF_LD + c;
        float* dst = out + (size_t)tok * H_DIM + n0 + c;
#pragma unroll
        for (int i = 0; i < 8; i++)
            atomicAdd(dst + i, w * src[i]);
    }
}

// ---------------- launch ----------------
extern "C" void kernel_launch(void* const* d_in, const int* in_sizes, int n_in,
                              void* d_out, int out_size) {
    const float* x  = (const float*)d_in[0];
    const float* gw = (const float*)d_in[1];
    const float* ew = (const float*)d_in[2];
    float* out = (float*)d_out;

    cudaFuncSetAttribute(gemm_f16_kernel, cudaFuncAttributeMaxDynamicSharedMemorySize, SMEM_TOTAL);

    convert_kernel<<<2048, 256>>>(x, ew, out);
    gate_kernel<<<1024, 256>>>(x, gw);
    scatter_kernel<<<32, 256>>>();
    gemm_f16_kernel<<<dim3(137, 8), 256, SMEM_TOTAL>>>(out);
}

// round 9
// speedup vs baseline: 1.3152x; 1.3152x over previous
#include <cuda_runtime.h>
#include <cuda_fp16.h>
#include <mma.h>
#include <math.h>
#include <stdint.h>

using namespace nvcuda;

#define B_TOK 8192
#define H_DIM 1024
#define N_EXP 8
#define MAX_ROWS 17536   // 137 tiles * 128

// ---------------- scratch (static device memory; no allocations) ----------------
__device__ __half g_x_f16[B_TOK * H_DIM];
__device__ __half g_w_f16[N_EXP * H_DIM * H_DIM];   // [e][k][n] native layout

__device__ int   g_tok_e[B_TOK * 2];
__device__ float g_tok_w[B_TOK * 2];
__device__ int   g_counts[N_EXP];
__device__ int   g_cursor[N_EXP];
__device__ int   g_poff[N_EXP + 1];
__device__ int   g_tileoff[N_EXP + 1];
__device__ int   g_rows_tok[MAX_ROWS];
__device__ int   g_pos[B_TOK * 2];
__device__ __half g_ybuf_h[(size_t)MAX_ROWS * H_DIM];   // fp16 expert outputs

// ---------------- helpers ----------------
#define CP_ASYNC16(dst, src) \
    asm volatile("cp.async.cg.shared.global [%0], [%1], 16;\n" :: "r"(dst), "l"(src))
#define CP_COMMIT() asm volatile("cp.async.commit_group;\n" ::: "memory")
#define CP_WAIT(n)  asm volatile("cp.async.wait_group %0;\n" :: "n"(n) : "memory")

__device__ __forceinline__ uint32_t smem_u32(const void* p) {
    uint32_t a;
    asm("{ .reg .u64 t; cvta.to.shared.u64 t, %1; cvt.u32.u64 %0, t; }" : "=r"(a) : "l"(p));
    return a;
}
__device__ __forceinline__ uint32_t h2_u32(__half2 h) {
    return *reinterpret_cast<uint32_t*>(&h);
}

// ---------------- convert (fp32 -> fp16, x and w) + init fold; 8 floats/tensor/iter ----------------
__global__ void convert_kernel(const float* __restrict__ x, const float* __restrict__ w) {
    int gid = blockIdx.x * blockDim.x + threadIdx.x;
    if (gid < N_EXP) { g_counts[gid] = 0; g_cursor[gid] = 0; }
    if (gid < MAX_ROWS) g_rows_tok[gid] = 0;

    const int n8 = (B_TOK * H_DIM) / 8;   // 1M chunks of 8 floats
    const int stride = gridDim.x * blockDim.x;
    for (int j = gid; j < n8; j += stride) {
        const float4* xp = reinterpret_cast<const float4*>(x) + 2 * j;
        float4 v0 = xp[0], v1 = xp[1];
        const float4* wp = reinterpret_cast<const float4*>(w) + 2 * j;
        float4 u0 = wp[0], u1 = wp[1];
        uint4 hx;
        hx.x = h2_u32(__floats2half2_rn(v0.x, v0.y));
        hx.y = h2_u32(__floats2half2_rn(v0.z, v0.w));
        hx.z = h2_u32(__floats2half2_rn(v1.x, v1.y));
        hx.w = h2_u32(__floats2half2_rn(v1.z, v1.w));
        reinterpret_cast<uint4*>(g_x_f16)[j] = hx;
        uint4 hw;
        hw.x = h2_u32(__floats2half2_rn(u0.x, u0.y));
        hw.y = h2_u32(__floats2half2_rn(u0.z, u0.w));
        hw.z = h2_u32(__floats2half2_rn(u1.x, u1.y));
        hw.w = h2_u32(__floats2half2_rn(u1.z, u1.w));
        reinterpret_cast<uint4*>(g_w_f16)[j] = hw;
    }
}

// ---------------- gate (R4/R7 exact) ----------------
__global__ void gate_kernel(const float* __restrict__ x, const float* __restrict__ gw) {
    __shared__ float sgw[N_EXP * H_DIM];
    int tid = threadIdx.x;
    for (int i = tid; i < N_EXP * H_DIM; i += blockDim.x) {
        int h = i >> 3, e = i & 7;
        sgw[e * H_DIM + h] = gw[i];
    }
    __syncthreads();
    int warp = tid >> 5, lane = tid & 31;
    int b = blockIdx.x * 8 + warp;
    const float* xr = x + (size_t)b * H_DIM;
    float acc[N_EXP];
#pragma unroll
    for (int e = 0; e < N_EXP; e++) acc[e] = 0.0f;
    for (int i = lane; i < H_DIM; i += 32) {
        float xv = xr[i];
#pragma unroll
        for (int e = 0; e < N_EXP; e++) acc[e] += xv * sgw[e * H_DIM + i];
    }
#pragma unroll
    for (int e = 0; e < N_EXP; e++) {
#pragma unroll
        for (int o = 16; o > 0; o >>= 1)
            acc[e] += __shfl_down_sync(0xffffffffu, acc[e], o);
    }
    if (lane == 0) {
        float b1v = -1e30f; int b1 = 0;
#pragma unroll
        for (int e = 0; e < N_EXP; e++)
            if (acc[e] > b1v) { b1v = acc[e]; b1 = e; }
        float b2v = -1e30f; int b2 = 0;
#pragma unroll
        for (int e = 0; e < N_EXP; e++)
            if (e != b1 && acc[e] > b2v) { b2v = acc[e]; b2 = e; }
        float e2 = expf(b2v - b1v);
        float inv = 1.0f / (1.0f + e2);
        g_tok_e[2 * b]     = b1;
        g_tok_e[2 * b + 1] = b2;
        g_tok_w[2 * b]     = inv;
        g_tok_w[2 * b + 1] = e2 * inv;
        atomicAdd(&g_counts[b1], 1);
        atomicAdd(&g_counts[b2], 1);
    }
}

// ---------------- scatter (R7 exact) ----------------
__global__ void scatter_kernel() {
    __shared__ int s_poff[N_EXP + 1];
    if (threadIdx.x == 0) {
        int po = 0, to = 0;
        int poff[N_EXP + 1], tilo[N_EXP + 1];
        for (int e = 0; e < N_EXP; e++) {
            poff[e] = po; tilo[e] = to;
            int t = (g_counts[e] + 127) >> 7;
            to += t;
            po += t << 7;
        }
        poff[N_EXP] = po; tilo[N_EXP] = to;
        for (int e = 0; e <= N_EXP; e++) s_poff[e] = poff[e];
        if (blockIdx.x == 0) {
            for (int e = 0; e <= N_EXP; e++) { g_poff[e] = poff[e]; g_tileoff[e] = tilo[e]; }
        }
    }
    __syncthreads();
    int b = blockIdx.x * blockDim.x + threadIdx.x;
    if (b >= B_TOK) return;
#pragma unroll
    for (int j = 0; j < 2; j++) {
        int e = g_tok_e[2 * b + j];
        int p = s_poff[e] + atomicAdd(&g_cursor[e], 1);
        g_rows_tok[p] = b;
        g_pos[2 * b + j] = p;
    }
}

// ---------------- grouped GEMM: R7 mainloop (wrap counters) + smem-staged fp16 epilogue ----------------
#define N_STAGE 3
#define SA_LD 72
#define SB_LD 136
#define SA_ST (128 * SA_LD)
#define SB_ST (64 * SB_LD)
#define SB_BASE (N_STAGE * SA_ST)
#define TOK_BASE_B ((N_STAGE * SA_ST + N_STAGE * SB_ST) * 2)
#define SMEM_TOTAL (TOK_BASE_B + 512)
#define SF_LD 132   // f32 staging row pitch (floats)

__global__ __launch_bounds__(256, 2) void gemm_f16_kernel() {
    int mt = blockIdx.x;
    if (mt >= g_tileoff[N_EXP]) return;
    int e = 0;
    while (mt >= g_tileoff[e + 1]) e++;
    int row0 = g_poff[e] + ((mt - g_tileoff[e]) << 7);
    int n0 = blockIdx.y << 7;

    extern __shared__ char smem[];
    __half* sA = reinterpret_cast<__half*>(smem);
    __half* sB = reinterpret_cast<__half*>(smem) + SB_BASE;
    int* s_tok = reinterpret_cast<int*>(smem + TOK_BASE_B);
    uint32_t sbase = smem_u32(smem);

    int tid = threadIdx.x;
    if (tid < 128) s_tok[tid] = g_rows_tok[row0 + tid];
    __syncthreads();

    const __half* wbase = g_w_f16 + (size_t)e * H_DIM * H_DIM + n0;

    auto do_load = [&](int st, int k0) {
        uint32_t aoff = sbase + (uint32_t)(st * SA_ST * 2);
        uint32_t boff = sbase + (uint32_t)((SB_BASE + st * SB_ST) * 2);
#pragma unroll
        for (int ii = 0; ii < 4; ii++) {
            int idx = tid + ii * 256;
            int ra = idx >> 3, ca = idx & 7;
            const char* asrc = (const char*)(g_x_f16 + (size_t)s_tok[ra] * H_DIM + k0) + ca * 16;
            CP_ASYNC16(aoff + (uint32_t)(ra * SA_LD + ca * 8) * 2, asrc);
            int rb = idx >> 4, cb = idx & 15;
            const char* bsrc = (const char*)(wbase + (size_t)(k0 + rb) * H_DIM) + cb * 16;
            CP_ASYNC16(boff + (uint32_t)(rb * SB_LD + cb * 8) * 2, bsrc);
        }
        CP_COMMIT();
    };

    int wid = tid >> 5;
    int wm = wid & 3;
    int wn = wid >> 2;

    wmma::fragment<wmma::accumulator, 16, 16, 16, float> acc[2][4];
#pragma unroll
    for (int f = 0; f < 2; f++)
#pragma unroll
        for (int j = 0; j < 4; j++) wmma::fill_fragment(acc[f][j], 0.0f);

    do_load(0, 0);
    do_load(1, 64);

    int st = 0;      // compute stage (wrap counter)
    int ld = 2;      // load stage (wrap counter)
    for (int it = 0; it < 16; it++) {
        if (it == 15) { CP_WAIT(0); } else { CP_WAIT(1); }
        __syncthreads();
        if (it + 2 < 16) do_load(ld, (it + 2) << 6);

        const __half* A0 = sA + st * SA_ST + (wm * 32) * SA_LD;
        const __half* B0 = sB + st * SB_ST + wn * 64;
#pragma unroll
        for (int ks = 0; ks < 4; ks++) {
            wmma::fragment<wmma::matrix_a, 16, 16, 16, __half, wmma::row_major> af[2];
            wmma::load_matrix_sync(af[0], A0 + ks * 16, SA_LD);
            wmma::load_matrix_sync(af[1], A0 + 16 * SA_LD + ks * 16, SA_LD);
#pragma unroll
            for (int j = 0; j < 4; j++) {
                wmma::fragment<wmma::matrix_b, 16, 16, 16, __half, wmma::row_major> bf;
                wmma::load_matrix_sync(bf, B0 + (ks * 16) * SB_LD + j * 16, SB_LD);
                wmma::mma_sync(acc[0][j], af[0], bf, acc[0][j]);
                wmma::mma_sync(acc[1][j], af[1], bf, acc[1][j]);
            }
        }
        st = (st + 1 == N_STAGE) ? 0 : st + 1;
        ld = (ld + 1 == N_STAGE) ? 0 : ld + 1;
    }

    // ---- epilogue: stage f32 accs into (now-dead) smem, then coalesced fp16 stores ----
    __syncthreads();
    float* sF = reinterpret_cast<float*>(smem);   // [128][SF_LD] = 67584 B
#pragma unroll
    for (int f = 0; f < 2; f++)
#pragma unroll
        for (int j = 0; j < 4; j++)
            wmma::store_matrix_sync(sF + (size_t)(wm * 32 + f * 16) * SF_LD + wn * 64 + j * 16,
                                    acc[f][j], SF_LD, wmma::mem_row_major);
    __syncthreads();
#pragma unroll
    for (int q = tid; q < 2048; q += 256) {
        int r = q >> 4;
        int c = (q & 15) << 3;
        const float* src = sF + (size_t)r * SF_LD + c;
        float4 f0 = *reinterpret_cast<const float4*>(src);
        float4 f1 = *reinterpret_cast<const float4*>(src + 4);
        uint4 h;
        h.x = h2_u32(__floats2half2_rn(f0.x, f0.y));
        h.y = h2_u32(__floats2half2_rn(f0.z, f0.w));
        h.z = h2_u32(__floats2half2_rn(f1.x, f1.y));
        h.w = h2_u32(__floats2half2_rn(f1.z, f1.w));
        *reinterpret_cast<uint4*>(g_ybuf_h + (size_t)(row0 + r) * H_DIM + n0 + c) = h;
    }
}

// ---------------- combine: out[b] = w0*y[p0] + w1*y[p1]  (16 halves/thread, MLP=4) ----------------
__global__ void combine_kernel(float* __restrict__ out) {
    int gid = blockIdx.x * blockDim.x + threadIdx.x;   // B_TOK*64 threads
    int b = gid >> 6;
    int c16 = (gid & 63) << 4;                          // start half index
    float w0 = g_tok_w[2 * b];
    float w1 = g_tok_w[2 * b + 1];
    int p0 = g_pos[2 * b];
    int p1 = g_pos[2 * b + 1];
    const uint4* ra = reinterpret_cast<const uint4*>(g_ybuf_h + (size_t)p0 * H_DIM + c16);
    const uint4* rb = reinterpret_cast<const uint4*>(g_ybuf_h + (size_t)p1 * H_DIM + c16);
    uint4 ya0 = ra[0], ya1 = ra[1];
    uint4 yb0 = rb[0], yb1 = rb[1];
    float* ob = out + (size_t)b * H_DIM + c16;

    float2 a, c;
    float4 o;
#define COMB(au, bu, dst)                                            \
    a = __half22float2(*reinterpret_cast<__half2*>(&(au)));          \
    c = __half22float2(*reinterpret_cast<__half2*>(&(bu)));          \
    (dst).x = w0 * a.x + w1 * c.x; (dst).y = w0 * a.y + w1 * c.y;

    { float4 o0, o1;
      COMB(ya0.x, yb0.x, o0); o.x = o0.x; o.y = o0.y;
      COMB(ya0.y, yb0.y, o1); o.z = o1.x; o.w = o1.y;
      reinterpret_cast<float4*>(ob)[0] = o;
      COMB(ya0.z, yb0.z, o0); o.x = o0.x; o.y = o0.y;
      COMB(ya0.w, yb0.w, o1); o.z = o1.x; o.w = o1.y;
      reinterpret_cast<float4*>(ob)[1] = o;
      COMB(ya1.x, yb1.x, o0); o.x = o0.x; o.y = o0.y;
      COMB(ya1.y, yb1.y, o1); o.z = o1.x; o.w = o1.y;
      reinterpret_cast<float4*>(ob)[2] = o;
      COMB(ya1.z, yb1.z, o0); o.x = o0.x; o.y = o0.y;
      COMB(ya1.w, yb1.w, o1); o.z = o1.x; o.w = o1.y;
      reinterpret_cast<float4*>(ob)[3] = o;
    }
#undef COMB
}

// ---------------- launch ----------------
extern "C" void kernel_launch(void* const* d_in, const int* in_sizes, int n_in,
                              void* d_out, int out_size) {
    const float* x  = (const float*)d_in[0];
    const float* gw = (const float*)d_in[1];
    const float* ew = (const float*)d_in[2];
    float* out = (float*)d_out;

    cudaFuncSetAttribute(gemm_f16_kernel, cudaFuncAttributeMaxDynamicSharedMemorySize, SMEM_TOTAL);

    convert_kernel<<<1024, 256>>>(x, ew);
    gate_kernel<<<1024, 256>>>(x, gw);
    scatter_kernel<<<32, 256>>>();
    gemm_f16_kernel<<<dim3(137, 8), 256, SMEM_TOTAL>>>();
    combine_kernel<<<2048, 256>>>(out);
}

// round 10
// speedup vs baseline: 1.3730x; 1.0439x over previous
#include <cuda_runtime.h>
#include <cuda_fp16.h>
#include <mma.h>
#include <math.h>
#include <stdint.h>

using namespace nvcuda;

#define B_TOK 8192
#define H_DIM 1024
#define N_EXP 8
#define MAX_ROWS 17536   // 137 tiles * 128

// ---------------- scratch (static device memory; no allocations) ----------------
__device__ __half g_x_f16[B_TOK * H_DIM];
__device__ __half g_w_f16[N_EXP * H_DIM * H_DIM];   // [e][k][n] native layout

__device__ int   g_tok_e[B_TOK * 2];
__device__ float g_tok_w[B_TOK * 2];
__device__ int   g_counts[N_EXP];
__device__ int   g_cursor[N_EXP];
__device__ int   g_poff[N_EXP + 1];
__device__ int   g_tileoff[N_EXP + 1];
__device__ int   g_rows_tok[MAX_ROWS];
__device__ int   g_pos[B_TOK * 2];
__device__ __half g_ybuf_h[(size_t)MAX_ROWS * H_DIM];   // fp16 expert outputs

// ---------------- helpers ----------------
#define CP_ASYNC16(dst, src) \
    asm volatile("cp.async.cg.shared.global [%0], [%1], 16;\n" :: "r"(dst), "l"(src))
#define CP_COMMIT() asm volatile("cp.async.commit_group;\n" ::: "memory")
#define CP_WAIT(n)  asm volatile("cp.async.wait_group %0;\n" :: "n"(n) : "memory")

__device__ __forceinline__ uint32_t smem_u32(const void* p) {
    uint32_t a;
    asm("{ .reg .u64 t; cvta.to.shared.u64 t, %1; cvt.u32.u64 %0, t; }" : "=r"(a) : "l"(p));
    return a;
}
__device__ __forceinline__ uint32_t h2_u32(__half2 h) {
    return *reinterpret_cast<uint32_t*>(&h);
}

// ---------------- convert (fp32 -> fp16, w ONLY) + init fold ----------------
__global__ void convert_kernel(const float* __restrict__ w) {
    int gid = blockIdx.x * blockDim.x + threadIdx.x;
    if (gid < N_EXP) { g_counts[gid] = 0; g_cursor[gid] = 0; }
    if (gid < MAX_ROWS) g_rows_tok[gid] = 0;

    const int n8 = (N_EXP * H_DIM * H_DIM) / 8;   // 1M chunks of 8 floats
    const int stride = gridDim.x * blockDim.x;
    for (int j = gid; j < n8; j += stride) {
        const float4* wp = reinterpret_cast<const float4*>(w) + 2 * j;
        float4 u0 = wp[0], u1 = wp[1];
        uint4 hw;
        hw.x = h2_u32(__floats2half2_rn(u0.x, u0.y));
        hw.y = h2_u32(__floats2half2_rn(u0.z, u0.w));
        hw.z = h2_u32(__floats2half2_rn(u1.x, u1.y));
        hw.w = h2_u32(__floats2half2_rn(u1.z, u1.w));
        reinterpret_cast<uint4*>(g_w_f16)[j] = hw;
    }
}

// ---------------- gate + fused x->fp16 conversion ----------------
__global__ void gate_kernel(const float* __restrict__ x, const float* __restrict__ gw) {
    __shared__ float sgw[N_EXP * H_DIM];  // transposed [e][h]
    int tid = threadIdx.x;
    for (int i = tid; i < N_EXP * H_DIM; i += blockDim.x) {
        int h = i >> 3, e = i & 7;
        sgw[e * H_DIM + h] = gw[i];
    }
    __syncthreads();
    int warp = tid >> 5, lane = tid & 31;
    int b = blockIdx.x * 8 + warp;
    const float* xr = x + (size_t)b * H_DIM;
    __half* xh = g_x_f16 + (size_t)b * H_DIM;
    float acc[N_EXP];
#pragma unroll
    for (int e = 0; e < N_EXP; e++) acc[e] = 0.0f;
    for (int i = lane; i < H_DIM; i += 32) {
        float xv = xr[i];
        xh[i] = __float2half_rn(xv);          // fused conversion (each token row once)
#pragma unroll
        for (int e = 0; e < N_EXP; e++) acc[e] += xv * sgw[e * H_DIM + i];
    }
#pragma unroll
    for (int e = 0; e < N_EXP; e++) {
#pragma unroll
        for (int o = 16; o > 0; o >>= 1)
            acc[e] += __shfl_down_sync(0xffffffffu, acc[e], o);
    }
    if (lane == 0) {
        float b1v = -1e30f; int b1 = 0;
#pragma unroll
        for (int e = 0; e < N_EXP; e++)
            if (acc[e] > b1v) { b1v = acc[e]; b1 = e; }
        float b2v = -1e30f; int b2 = 0;
#pragma unroll
        for (int e = 0; e < N_EXP; e++)
            if (e != b1 && acc[e] > b2v) { b2v = acc[e]; b2 = e; }
        float e2 = expf(b2v - b1v);
        float inv = 1.0f / (1.0f + e2);
        g_tok_e[2 * b]     = b1;
        g_tok_e[2 * b + 1] = b2;
        g_tok_w[2 * b]     = inv;
        g_tok_w[2 * b + 1] = e2 * inv;
        atomicAdd(&g_counts[b1], 1);
        atomicAdd(&g_counts[b2], 1);
    }
}

// ---------------- scatter: two-level (smem ranks + one ATOMG/expert/block) ----------------
__global__ void scatter_kernel() {
    __shared__ int s_poff[N_EXP + 1];
    __shared__ int s_cnt[N_EXP];
    __shared__ int s_base[N_EXP];
    int tid = threadIdx.x;
    if (tid == 0) {
        int po = 0, to = 0;
        int poff[N_EXP + 1], tilo[N_EXP + 1];
        for (int e = 0; e < N_EXP; e++) {
            poff[e] = po; tilo[e] = to;
            int t = (g_counts[e] + 127) >> 7;
            to += t;
            po += t << 7;
        }
        poff[N_EXP] = po; tilo[N_EXP] = to;
        for (int e = 0; e <= N_EXP; e++) s_poff[e] = poff[e];
        if (blockIdx.x == 0) {
            for (int e = 0; e <= N_EXP; e++) { g_poff[e] = poff[e]; g_tileoff[e] = tilo[e]; }
        }
    }
    if (tid < N_EXP) s_cnt[tid] = 0;
    __syncthreads();

    int b = blockIdx.x * blockDim.x + tid;
    int e0 = g_tok_e[2 * b], e1 = g_tok_e[2 * b + 1];
    int r0 = atomicAdd(&s_cnt[e0], 1);
    int r1 = atomicAdd(&s_cnt[e1], 1);
    __syncthreads();
    if (tid < N_EXP) s_base[tid] = atomicAdd(&g_cursor[tid], s_cnt[tid]);
    __syncthreads();

    int p0 = s_poff[e0] + s_base[e0] + r0;
    int p1 = s_poff[e1] + s_base[e1] + r1;
    g_rows_tok[p0] = b;
    g_rows_tok[p1] = b;
    g_pos[2 * b]     = p0;
    g_pos[2 * b + 1] = p1;
}

// ---------------- grouped GEMM (R9 exact): 128x128 tile, 3-stage cp.async, smem-staged fp16 epilogue ----------------
#define N_STAGE 3
#define SA_LD 72
#define SB_LD 136
#define SA_ST (128 * SA_LD)
#define SB_ST (64 * SB_LD)
#define SB_BASE (N_STAGE * SA_ST)
#define TOK_BASE_B ((N_STAGE * SA_ST + N_STAGE * SB_ST) * 2)
#define SMEM_TOTAL (TOK_BASE_B + 512)
#define SF_LD 132   // f32 staging row pitch (floats)

__global__ __launch_bounds__(256, 2) void gemm_f16_kernel() {
    int mt = blockIdx.x;
    if (mt >= g_tileoff[N_EXP]) return;
    int e = 0;
    while (mt >= g_tileoff[e + 1]) e++;
    int row0 = g_poff[e] + ((mt - g_tileoff[e]) << 7);
    int n0 = blockIdx.y << 7;

    extern __shared__ char smem[];
    __half* sA = reinterpret_cast<__half*>(smem);
    __half* sB = reinterpret_cast<__half*>(smem) + SB_BASE;
    int* s_tok = reinterpret_cast<int*>(smem + TOK_BASE_B);
    uint32_t sbase = smem_u32(smem);

    int tid = threadIdx.x;
    if (tid < 128) s_tok[tid] = g_rows_tok[row0 + tid];
    __syncthreads();

    const __half* wbase = g_w_f16 + (size_t)e * H_DIM * H_DIM + n0;

    auto do_load = [&](int st, int k0) {
        uint32_t aoff = sbase + (uint32_t)(st * SA_ST * 2);
        uint32_t boff = sbase + (uint32_t)((SB_BASE + st * SB_ST) * 2);
#pragma unroll
        for (int ii = 0; ii < 4; ii++) {
            int idx = tid + ii * 256;
            int ra = idx >> 3, ca = idx & 7;
            const char* asrc = (const char*)(g_x_f16 + (size_t)s_tok[ra] * H_DIM + k0) + ca * 16;
            CP_ASYNC16(aoff + (uint32_t)(ra * SA_LD + ca * 8) * 2, asrc);
            int rb = idx >> 4, cb = idx & 15;
            const char* bsrc = (const char*)(wbase + (size_t)(k0 + rb) * H_DIM) + cb * 16;
            CP_ASYNC16(boff + (uint32_t)(rb * SB_LD + cb * 8) * 2, bsrc);
        }
        CP_COMMIT();
    };

    int wid = tid >> 5;
    int wm = wid & 3;
    int wn = wid >> 2;

    wmma::fragment<wmma::accumulator, 16, 16, 16, float> acc[2][4];
#pragma unroll
    for (int f = 0; f < 2; f++)
#pragma unroll
        for (int j = 0; j < 4; j++) wmma::fill_fragment(acc[f][j], 0.0f);

    do_load(0, 0);
    do_load(1, 64);

    int st = 0;
    int ld = 2;
    for (int it = 0; it < 16; it++) {
        if (it == 15) { CP_WAIT(0); } else { CP_WAIT(1); }
        __syncthreads();
        if (it + 2 < 16) do_load(ld, (it + 2) << 6);

        const __half* A0 = sA + st * SA_ST + (wm * 32) * SA_LD;
        const __half* B0 = sB + st * SB_ST + wn * 64;
#pragma unroll
        for (int ks = 0; ks < 4; ks++) {
            wmma::fragment<wmma::matrix_a, 16, 16, 16, __half, wmma::row_major> af[2];
            wmma::load_matrix_sync(af[0], A0 + ks * 16, SA_LD);
            wmma::load_matrix_sync(af[1], A0 + 16 * SA_LD + ks * 16, SA_LD);
#pragma unroll
            for (int j = 0; j < 4; j++) {
                wmma::fragment<wmma::matrix_b, 16, 16, 16, __half, wmma::row_major> bf;
                wmma::load_matrix_sync(bf, B0 + (ks * 16) * SB_LD + j * 16, SB_LD);
                wmma::mma_sync(acc[0][j], af[0], bf, acc[0][j]);
                wmma::mma_sync(acc[1][j], af[1], bf, acc[1][j]);
            }
        }
        st = (st + 1 == N_STAGE) ? 0 : st + 1;
        ld = (ld + 1 == N_STAGE) ? 0 : ld + 1;
    }

    __syncthreads();
    float* sF = reinterpret_cast<float*>(smem);
#pragma unroll
    for (int f = 0; f < 2; f++)
#pragma unroll
        for (int j = 0; j < 4; j++)
            wmma::store_matrix_sync(sF + (size_t)(wm * 32 + f * 16) * SF_LD + wn * 64 + j * 16,
                                    acc[f][j], SF_LD, wmma::mem_row_major);
    __syncthreads();
#pragma unroll
    for (int q = tid; q < 2048; q += 256) {
        int r = q >> 4;
        int c = (q & 15) << 3;
        const float* src = sF + (size_t)r * SF_LD + c;
        float4 f0 = *reinterpret_cast<const float4*>(src);
        float4 f1 = *reinterpret_cast<const float4*>(src + 4);
        uint4 h;
        h.x = h2_u32(__floats2half2_rn(f0.x, f0.y));
        h.y = h2_u32(__floats2half2_rn(f0.z, f0.w));
        h.z = h2_u32(__floats2half2_rn(f1.x, f1.y));
        h.w = h2_u32(__floats2half2_rn(f1.z, f1.w));
        *reinterpret_cast<uint4*>(g_ybuf_h + (size_t)(row0 + r) * H_DIM + n0 + c) = h;
    }
}

// ---------------- combine: out[b] = w0*y[p0] + w1*y[p1]  (16 halves/thread) ----------------
__global__ void combine_kernel(float* __restrict__ out) {
    int gid = blockIdx.x * blockDim.x + threadIdx.x;
    int b = gid >> 6;
    int c16 = (gid & 63) << 4;
    float2 w = *reinterpret_cast<const float2*>(g_tok_w + 2 * b);
    int2 p = *reinterpret_cast<const int2*>(g_pos + 2 * b);
    float w0 = w.x, w1 = w.y;
    const uint4* ra = reinterpret_cast<const uint4*>(g_ybuf_h + (size_t)p.x * H_DIM + c16);
    const uint4* rb = reinterpret_cast<const uint4*>(g_ybuf_h + (size_t)p.y * H_DIM + c16);
    uint4 ya0 = ra[0], ya1 = ra[1];
    uint4 yb0 = rb[0], yb1 = rb[1];
    float* ob = out + (size_t)b * H_DIM + c16;

    float2 a, c;
    float4 o;
#define COMB2(au, bu, ox, oy)                                        \
    a = __half22float2(*reinterpret_cast<__half2*>(&(au)));          \
    c = __half22float2(*reinterpret_cast<__half2*>(&(bu)));          \
    ox = w0 * a.x + w1 * c.x; oy = w0 * a.y + w1 * c.y;

    COMB2(ya0.x, yb0.x, o.x, o.y); COMB2(ya0.y, yb0.y, o.z, o.w);
    reinterpret_cast<float4*>(ob)[0] = o;
    COMB2(ya0.z, yb0.z, o.x, o.y); COMB2(ya0.w, yb0.w, o.z, o.w);
    reinterpret_cast<float4*>(ob)[1] = o;
    COMB2(ya1.x, yb1.x, o.x, o.y); COMB2(ya1.y, yb1.y, o.z, o.w);
    reinterpret_cast<float4*>(ob)[2] = o;
    COMB2(ya1.z, yb1.z, o.x, o.y); COMB2(ya1.w, yb1.w, o.z, o.w);
    reinterpret_cast<float4*>(ob)[3] = o;
#undef COMB2
}

// ---------------- launch ----------------
extern "C" void kernel_launch(void* const* d_in, const int* in_sizes, int n_in,
                              void* d_out, int out_size) {
    const float* x  = (const float*)d_in[0];
    const float* gw = (const float*)d_in[1];
    const float* ew = (const float*)d_in[2];
    float* out = (float*)d_out;

    cudaFuncSetAttribute(gemm_f16_kernel, cudaFuncAttributeMaxDynamicSharedMemorySize, SMEM_TOTAL);

    convert_kernel<<<2048, 256>>>(ew);
    gate_kernel<<<1024, 256>>>(x, gw);
    scatter_kernel<<<32, 256>>>();
    gemm_f16_kernel<<<dim3(137, 8), 256, SMEM_TOTAL>>>();
    combine_kernel<<<2048, 256>>>(out);
}

// round 12
// speedup vs baseline: 1.4470x; 1.0539x over previous
#include <cuda_runtime.h>
#include <cuda_fp16.h>
#include <mma.h>
#include <math.h>
#include <stdint.h>

using namespace nvcuda;

#define B_TOK 8192
#define H_DIM 1024
#define N_EXP 8
#define MAX_ROWS 17536   // 137 tiles * 128

// ---------------- scratch (static device memory; no allocations) ----------------
// NOTE: g_counts/g_cursor start zero (static init) and are re-zeroed at the end
// of combine_kernel each call, so every kernel_launch sees them zeroed.
__device__ __half g_x_f16[B_TOK * H_DIM];
__device__ __half g_w_f16[N_EXP * H_DIM * H_DIM];   // [e][k][n] native layout

__device__ int   g_tok_e[B_TOK * 2];
__device__ float g_tok_w[B_TOK * 2];
__device__ int   g_counts[N_EXP];
__device__ int   g_cursor[N_EXP];
__device__ int   g_poff[N_EXP + 1];
__device__ int   g_tileoff[N_EXP + 1];
__device__ int   g_rows_tok[MAX_ROWS];   // stale values stay in [0,B_TOK) => always safe
__device__ int   g_pos[B_TOK * 2];
__device__ __half g_ybuf_h[(size_t)MAX_ROWS * H_DIM];   // fp16 expert outputs

// ---------------- helpers ----------------
#define CP_ASYNC16(dst, src) \
    asm volatile("cp.async.cg.shared.global [%0], [%1], 16;\n" :: "r"(dst), "l"(src))
#define CP_COMMIT() asm volatile("cp.async.commit_group;\n" ::: "memory")
#define CP_WAIT(n)  asm volatile("cp.async.wait_group %0;\n" :: "n"(n) : "memory")

__device__ __forceinline__ uint32_t smem_u32(const void* p) {
    uint32_t a;
    asm("{ .reg .u64 t; cvta.to.shared.u64 t, %1; cvt.u32.u64 %0, t; }" : "=r"(a) : "l"(p));
    return a;
}
__device__ __forceinline__ uint32_t h2_u32(__half2 h) {
    return *reinterpret_cast<uint32_t*>(&h);
}

// ---------------- prep: gate (+x->fp16) blocks [0,1024) || w->fp16 blocks [1024,3072) ----------------
__global__ void prep_kernel(const float* __restrict__ x,
                            const float* __restrict__ w,
                            const float* __restrict__ gw) {
    int tid = threadIdx.x;

    if (blockIdx.x >= 1024) {
        // ---- W convert ----
        int gid = (blockIdx.x - 1024) * blockDim.x + tid;   // 0..524287
        const int n8 = (N_EXP * H_DIM * H_DIM) / 8;         // 1M chunks of 8 floats
        const int stride = 2048 * blockDim.x;
        for (int j = gid; j < n8; j += stride) {
            const float4* wp = reinterpret_cast<const float4*>(w) + 2 * j;
            float4 u0 = wp[0], u1 = wp[1];
            uint4 hw;
            hw.x = h2_u32(__floats2half2_rn(u0.x, u0.y));
            hw.y = h2_u32(__floats2half2_rn(u0.z, u0.w));
            hw.z = h2_u32(__floats2half2_rn(u1.x, u1.y));
            hw.w = h2_u32(__floats2half2_rn(u1.z, u1.w));
            reinterpret_cast<uint4*>(g_w_f16)[j] = hw;
        }
        return;
    }

    // ---- gate + fused x->fp16 (counts are pre-zeroed by previous combine / static init) ----
    __shared__ float sgw[N_EXP * H_DIM];
    for (int i = tid; i < N_EXP * H_DIM; i += blockDim.x) {
        int h = i >> 3, e = i & 7;
        sgw[e * H_DIM + h] = gw[i];
    }
    __syncthreads();
    int warp = tid >> 5, lane = tid & 31;
    int b = blockIdx.x * 8 + warp;
    const float* xr = x + (size_t)b * H_DIM;
    __half* xh = g_x_f16 + (size_t)b * H_DIM;
    float acc[N_EXP];
#pragma unroll
    for (int e = 0; e < N_EXP; e++) acc[e] = 0.0f;
    for (int i = lane; i < H_DIM; i += 32) {
        float xv = xr[i];
        xh[i] = __float2half_rn(xv);
#pragma unroll
        for (int e = 0; e < N_EXP; e++) acc[e] += xv * sgw[e * H_DIM + i];
    }
#pragma unroll
    for (int e = 0; e < N_EXP; e++) {
#pragma unroll
        for (int o = 16; o > 0; o >>= 1)
            acc[e] += __shfl_down_sync(0xffffffffu, acc[e], o);
    }
    if (lane == 0) {
        float b1v = -1e30f; int b1 = 0;
#pragma unroll
        for (int e = 0; e < N_EXP; e++)
            if (acc[e] > b1v) { b1v = acc[e]; b1 = e; }
        float b2v = -1e30f; int b2 = 0;
#pragma unroll
        for (int e = 0; e < N_EXP; e++)
            if (e != b1 && acc[e] > b2v) { b2v = acc[e]; b2 = e; }
        float e2 = expf(b2v - b1v);
        float inv = 1.0f / (1.0f + e2);
        g_tok_e[2 * b]     = b1;
        g_tok_e[2 * b + 1] = b2;
        g_tok_w[2 * b]     = inv;
        g_tok_w[2 * b + 1] = e2 * inv;
        atomicAdd(&g_counts[b1], 1);
        atomicAdd(&g_counts[b2], 1);
    }
}

// ---------------- scatter: two-level (smem ranks + one ATOMG/expert/block) ----------------
__global__ void scatter_kernel() {
    __shared__ int s_poff[N_EXP + 1];
    __shared__ int s_cnt[N_EXP];
    __shared__ int s_base[N_EXP];
    int tid = threadIdx.x;
    if (tid == 0) {
        int po = 0, to = 0;
        int poff[N_EXP + 1], tilo[N_EXP + 1];
        for (int e = 0; e < N_EXP; e++) {
            poff[e] = po; tilo[e] = to;
            int t = (g_counts[e] + 127) >> 7;
            to += t;
            po += t << 7;
        }
        poff[N_EXP] = po; tilo[N_EXP] = to;
        for (int e = 0; e <= N_EXP; e++) s_poff[e] = poff[e];
        if (blockIdx.x == 0) {
            for (int e = 0; e <= N_EXP; e++) { g_poff[e] = poff[e]; g_tileoff[e] = tilo[e]; }
        }
    }
    if (tid < N_EXP) s_cnt[tid] = 0;
    __syncthreads();

    int b = blockIdx.x * blockDim.x + tid;
    int e0 = g_tok_e[2 * b], e1 = g_tok_e[2 * b + 1];
    int r0 = atomicAdd(&s_cnt[e0], 1);
    int r1 = atomicAdd(&s_cnt[e1], 1);
    __syncthreads();
    if (tid < N_EXP) s_base[tid] = atomicAdd(&g_cursor[tid], s_cnt[tid]);
    __syncthreads();

    int p0 = s_poff[e0] + s_base[e0] + r0;
    int p1 = s_poff[e1] + s_base[e1] + r1;
    g_rows_tok[p0] = b;
    g_rows_tok[p1] = b;
    g_pos[2 * b]     = p0;
    g_pos[2 * b + 1] = p1;
}

// ---------------- grouped GEMM (R9/R10 exact — DO NOT TOUCH) ----------------
#define N_STAGE 3
#define SA_LD 72
#define SB_LD 136
#define SA_ST (128 * SA_LD)
#define SB_ST (64 * SB_LD)
#define SB_BASE (N_STAGE * SA_ST)
#define TOK_BASE_B ((N_STAGE * SA_ST + N_STAGE * SB_ST) * 2)
#define SMEM_TOTAL (TOK_BASE_B + 512)
#define SF_LD 132

__global__ __launch_bounds__(256, 2) void gemm_f16_kernel() {
    int mt = blockIdx.x;
    if (mt >= g_tileoff[N_EXP]) return;
    int e = 0;
    while (mt >= g_tileoff[e + 1]) e++;
    int row0 = g_poff[e] + ((mt - g_tileoff[e]) << 7);
    int n0 = blockIdx.y << 7;

    extern __shared__ char smem[];
    __half* sA = reinterpret_cast<__half*>(smem);
    __half* sB = reinterpret_cast<__half*>(smem) + SB_BASE;
    int* s_tok = reinterpret_cast<int*>(smem + TOK_BASE_B);
    uint32_t sbase = smem_u32(smem);

    int tid = threadIdx.x;
    if (tid < 128) s_tok[tid] = g_rows_tok[row0 + tid];
    __syncthreads();

    const __half* wbase = g_w_f16 + (size_t)e * H_DIM * H_DIM + n0;

    auto do_load = [&](int st, int k0) {
        uint32_t aoff = sbase + (uint32_t)(st * SA_ST * 2);
        uint32_t boff = sbase + (uint32_t)((SB_BASE + st * SB_ST) * 2);
#pragma unroll
        for (int ii = 0; ii < 4; ii++) {
            int idx = tid + ii * 256;
            int ra = idx >> 3, ca = idx & 7;
            const char* asrc = (const char*)(g_x_f16 + (size_t)s_tok[ra] * H_DIM + k0) + ca * 16;
            CP_ASYNC16(aoff + (uint32_t)(ra * SA_LD + ca * 8) * 2, asrc);
            int rb = idx >> 4, cb = idx & 15;
            const char* bsrc = (const char*)(wbase + (size_t)(k0 + rb) * H_DIM) + cb * 16;
            CP_ASYNC16(boff + (uint32_t)(rb * SB_LD + cb * 8) * 2, bsrc);
        }
        CP_COMMIT();
    };

    int wid = tid >> 5;
    int wm = wid & 3;
    int wn = wid >> 2;

    wmma::fragment<wmma::accumulator, 16, 16, 16, float> acc[2][4];
#pragma unroll
    for (int f = 0; f < 2; f++)
#pragma unroll
        for (int j = 0; j < 4; j++) wmma::fill_fragment(acc[f][j], 0.0f);

    do_load(0, 0);
    do_load(1, 64);

    int st = 0;
    int ld = 2;
    for (int it = 0; it < 16; it++) {
        if (it == 15) { CP_WAIT(0); } else { CP_WAIT(1); }
        __syncthreads();
        if (it + 2 < 16) do_load(ld, (it + 2) << 6);

        const __half* A0 = sA + st * SA_ST + (wm * 32) * SA_LD;
        const __half* B0 = sB + st * SB_ST + wn * 64;
#pragma unroll
        for (int ks = 0; ks < 4; ks++) {
            wmma::fragment<wmma::matrix_a, 16, 16, 16, __half, wmma::row_major> af[2];
            wmma::load_matrix_sync(af[0], A0 + ks * 16, SA_LD);
            wmma::load_matrix_sync(af[1], A0 + 16 * SA_LD + ks * 16, SA_LD);
#pragma unroll
            for (int j = 0; j < 4; j++) {
                wmma::fragment<wmma::matrix_b, 16, 16, 16, __half, wmma::row_major> bf;
                wmma::load_matrix_sync(bf, B0 + (ks * 16) * SB_LD + j * 16, SB_LD);
                wmma::mma_sync(acc[0][j], af[0], bf, acc[0][j]);
                wmma::mma_sync(acc[1][j], af[1], bf, acc[1][j]);
            }
        }
        st = (st + 1 == N_STAGE) ? 0 : st + 1;
        ld = (ld + 1 == N_STAGE) ? 0 : ld + 1;
    }

    __syncthreads();
    float* sF = reinterpret_cast<float*>(smem);
#pragma unroll
    for (int f = 0; f < 2; f++)
#pragma unroll
        for (int j = 0; j < 4; j++)
            wmma::store_matrix_sync(sF + (size_t)(wm * 32 + f * 16) * SF_LD + wn * 64 + j * 16,
                                    acc[f][j], SF_LD, wmma::mem_row_major);
    __syncthreads();
#pragma unroll
    for (int q = tid; q < 2048; q += 256) {
        int r = q >> 4;
        int c = (q & 15) << 3;
        const float* src = sF + (size_t)r * SF_LD + c;
        float4 f0 = *reinterpret_cast<const float4*>(src);
        float4 f1 = *reinterpret_cast<const float4*>(src + 4);
        uint4 h;
        h.x = h2_u32(__floats2half2_rn(f0.x, f0.y));
        h.y = h2_u32(__floats2half2_rn(f0.z, f0.w));
        h.z = h2_u32(__floats2half2_rn(f1.x, f1.y));
        h.w = h2_u32(__floats2half2_rn(f1.z, f1.w));
        *reinterpret_cast<uint4*>(g_ybuf_h + (size_t)(row0 + r) * H_DIM + n0 + c) = h;
    }
}

// ---------------- combine: out[b] = w0*y[p0] + w1*y[p1]; resets counters for next call ----------------
__global__ void combine_kernel(float* __restrict__ out) {
    int gid = blockIdx.x * blockDim.x + threadIdx.x;
    if (gid < N_EXP) { g_counts[gid] = 0; g_cursor[gid] = 0; }   // pre-zero for next launch
    int b = gid >> 6;
    int c16 = (gid & 63) << 4;
    float2 w = *reinterpret_cast<const float2*>(g_tok_w + 2 * b);
    int2 p = *reinterpret_cast<const int2*>(g_pos + 2 * b);
    float w0 = w.x, w1 = w.y;
    const uint4* ra = reinterpret_cast<const uint4*>(g_ybuf_h + (size_t)p.x * H_DIM + c16);
    const uint4* rb = reinterpret_cast<const uint4*>(g_ybuf_h + (size_t)p.y * H_DIM + c16);
    uint4 ya0 = ra[0], ya1 = ra[1];
    uint4 yb0 = rb[0], yb1 = rb[1];
    float* ob = out + (size_t)b * H_DIM + c16;

    float2 a, c;
    float4 o;
#define COMB2(au, bu, ox, oy)                                        \
    a = __half22float2(*reinterpret_cast<__half2*>(&(au)));          \
    c = __half22float2(*reinterpret_cast<__half2*>(&(bu)));          \
    ox = w0 * a.x + w1 * c.x; oy = w0 * a.y + w1 * c.y;

    COMB2(ya0.x, yb0.x, o.x, o.y); COMB2(ya0.y, yb0.y, o.z, o.w);
    reinterpret_cast<float4*>(ob)[0] = o;
    COMB2(ya0.z, yb0.z, o.x, o.y); COMB2(ya0.w, yb0.w, o.z, o.w);
    reinterpret_cast<float4*>(ob)[1] = o;
    COMB2(ya1.x, yb1.x, o.x, o.y); COMB2(ya1.y, yb1.y, o.z, o.w);
    reinterpret_cast<float4*>(ob)[2] = o;
    COMB2(ya1.z, yb1.z, o.x, o.y); COMB2(ya1.w, yb1.w, o.z, o.w);
    reinterpret_cast<float4*>(ob)[3] = o;
#undef COMB2
}

// ---------------- launch ----------------
extern "C" void kernel_launch(void* const* d_in, const int* in_sizes, int n_in,
                              void* d_out, int out_size) {
    const float* x  = (const float*)d_in[0];
    const float* gw = (const float*)d_in[1];
    const float* ew = (const float*)d_in[2];
    float* out = (float*)d_out;

    cudaFuncSetAttribute(gemm_f16_kernel, cudaFuncAttributeMaxDynamicSharedMemorySize, SMEM_TOTAL);

    prep_kernel<<<3072, 256>>>(x, ew, gw);
    scatter_kernel<<<32, 256>>>();
    gemm_f16_kernel<<<dim3(137, 8), 256, SMEM_TOTAL>>>();
    combine_kernel<<<2048, 256>>>(out);
}

// round 13
// speedup vs baseline: 1.4473x; 1.0002x over previous
#include <cuda_runtime.h>
#include <cuda_fp16.h>
#include <mma.h>
#include <math.h>
#include <stdint.h>

using namespace nvcuda;

#define B_TOK 8192
#define H_DIM 1024
#define N_EXP 8
#define MAX_ROWS 17536   // 137 tiles * 128

// ---------------- scratch (static device memory; no allocations) ----------------
// NOTE: g_counts/g_cursor start zero (static init) and are re-zeroed at the end
// of combine_kernel each call, so every kernel_launch sees them zeroed.
__device__ __half g_x_f16[B_TOK * H_DIM];
__device__ __half g_w_f16[N_EXP * H_DIM * H_DIM];   // [e][k][n] native layout

__device__ int   g_tok_e[B_TOK * 2];
__device__ float g_tok_w[B_TOK * 2];
__device__ int   g_counts[N_EXP];
__device__ int   g_cursor[N_EXP];
__device__ int   g_poff[N_EXP + 1];
__device__ int   g_tileoff[N_EXP + 1];
__device__ int   g_rows_tok[MAX_ROWS];   // stale values stay in [0,B_TOK) => always safe
__device__ int   g_pos[B_TOK * 2];
__device__ __half g_ybuf_h[(size_t)MAX_ROWS * H_DIM];   // fp16 expert outputs

// ---------------- helpers ----------------
#define CP_ASYNC16(dst, src) \
    asm volatile("cp.async.cg.shared.global [%0], [%1], 16;\n" :: "r"(dst), "l"(src))
#define CP_COMMIT() asm volatile("cp.async.commit_group;\n" ::: "memory")
#define CP_WAIT(n)  asm volatile("cp.async.wait_group %0;\n" :: "n"(n) : "memory")

__device__ __forceinline__ uint32_t smem_u32(const void* p) {
    uint32_t a;
    asm("{ .reg .u64 t; cvta.to.shared.u64 t, %1; cvt.u32.u64 %0, t; }" : "=r"(a) : "l"(p));
    return a;
}
__device__ __forceinline__ uint32_t h2_u32(__half2 h) {
    return *reinterpret_cast<uint32_t*>(&h);
}

// ---------------- prep: gate (+x->fp16) blocks [0,1024) || w->fp16 blocks [1024,3072) ----------------
__global__ void prep_kernel(const float* __restrict__ x,
                            const float* __restrict__ w,
                            const float* __restrict__ gw) {
    int tid = threadIdx.x;

    if (blockIdx.x >= 1024) {
        // ---- W convert ----
        int gid = (blockIdx.x - 1024) * blockDim.x + tid;   // 0..524287
        const int n8 = (N_EXP * H_DIM * H_DIM) / 8;         // 1M chunks of 8 floats
        const int stride = 2048 * blockDim.x;
        for (int j = gid; j < n8; j += stride) {
            const float4* wp = reinterpret_cast<const float4*>(w) + 2 * j;
            float4 u0 = wp[0], u1 = wp[1];
            uint4 hw;
            hw.x = h2_u32(__floats2half2_rn(u0.x, u0.y));
            hw.y = h2_u32(__floats2half2_rn(u0.z, u0.w));
            hw.z = h2_u32(__floats2half2_rn(u1.x, u1.y));
            hw.w = h2_u32(__floats2half2_rn(u1.z, u1.w));
            reinterpret_cast<uint4*>(g_w_f16)[j] = hw;
        }
        return;
    }

    // ---- gate + fused x->fp16 (counts pre-zeroed by previous combine / static init) ----
    __shared__ float sgw[N_EXP * H_DIM];
    for (int i = tid; i < N_EXP * H_DIM; i += blockDim.x) {
        int h = i >> 3, e = i & 7;
        sgw[e * H_DIM + h] = gw[i];
    }
    __syncthreads();
    int warp = tid >> 5, lane = tid & 31;
    int b = blockIdx.x * 8 + warp;
    const float* xr = x + (size_t)b * H_DIM;
    __half* xh = g_x_f16 + (size_t)b * H_DIM;
    float acc[N_EXP];
#pragma unroll
    for (int e = 0; e < N_EXP; e++) acc[e] = 0.0f;
    for (int i = lane; i < H_DIM; i += 32) {
        float xv = xr[i];
        xh[i] = __float2half_rn(xv);
#pragma unroll
        for (int e = 0; e < N_EXP; e++) acc[e] += xv * sgw[e * H_DIM + i];
    }
#pragma unroll
    for (int e = 0; e < N_EXP; e++) {
#pragma unroll
        for (int o = 16; o > 0; o >>= 1)
            acc[e] += __shfl_down_sync(0xffffffffu, acc[e], o);
    }
    if (lane == 0) {
        float b1v = -1e30f; int b1 = 0;
#pragma unroll
        for (int e = 0; e < N_EXP; e++)
            if (acc[e] > b1v) { b1v = acc[e]; b1 = e; }
        float b2v = -1e30f; int b2 = 0;
#pragma unroll
        for (int e = 0; e < N_EXP; e++)
            if (e != b1 && acc[e] > b2v) { b2v = acc[e]; b2 = e; }
        float e2 = expf(b2v - b1v);
        float inv = 1.0f / (1.0f + e2);
        g_tok_e[2 * b]     = b1;
        g_tok_e[2 * b + 1] = b2;
        g_tok_w[2 * b]     = inv;
        g_tok_w[2 * b + 1] = e2 * inv;
        atomicAdd(&g_counts[b1], 1);
        atomicAdd(&g_counts[b2], 1);
    }
}

// ---------------- scatter: two-level (smem ranks + one ATOMG/expert/block) ----------------
__global__ void scatter_kernel() {
    __shared__ int s_poff[N_EXP + 1];
    __shared__ int s_cnt[N_EXP];
    __shared__ int s_base[N_EXP];
    int tid = threadIdx.x;
    if (tid == 0) {
        int po = 0, to = 0;
        int poff[N_EXP + 1], tilo[N_EXP + 1];
        for (int e = 0; e < N_EXP; e++) {
            poff[e] = po; tilo[e] = to;
            int t = (g_counts[e] + 127) >> 7;
            to += t;
            po += t << 7;
        }
        poff[N_EXP] = po; tilo[N_EXP] = to;
        for (int e = 0; e <= N_EXP; e++) s_poff[e] = poff[e];
        if (blockIdx.x == 0) {
            for (int e = 0; e <= N_EXP; e++) { g_poff[e] = poff[e]; g_tileoff[e] = tilo[e]; }
        }
    }
    if (tid < N_EXP) s_cnt[tid] = 0;
    __syncthreads();

    int b = blockIdx.x * blockDim.x + tid;
    int e0 = g_tok_e[2 * b], e1 = g_tok_e[2 * b + 1];
    int r0 = atomicAdd(&s_cnt[e0], 1);
    int r1 = atomicAdd(&s_cnt[e1], 1);
    __syncthreads();
    if (tid < N_EXP) s_base[tid] = atomicAdd(&g_cursor[tid], s_cnt[tid]);
    __syncthreads();

    int p0 = s_poff[e0] + s_base[e0] + r0;
    int p1 = s_poff[e1] + s_base[e1] + r1;
    g_rows_tok[p0] = b;
    g_rows_tok[p1] = b;
    g_pos[2 * b]     = p0;
    g_pos[2 * b + 1] = p1;
}

// ---------------- grouped GEMM (R9-R12 exact — DO NOT TOUCH) ----------------
#define N_STAGE 3
#define SA_LD 72
#define SB_LD 136
#define SA_ST (128 * SA_LD)
#define SB_ST (64 * SB_LD)
#define SB_BASE (N_STAGE * SA_ST)
#define TOK_BASE_B ((N_STAGE * SA_ST + N_STAGE * SB_ST) * 2)
#define SMEM_TOTAL (TOK_BASE_B + 512)
#define SF_LD 132

__global__ __launch_bounds__(256, 2) void gemm_f16_kernel() {
    int mt = blockIdx.x;
    if (mt >= g_tileoff[N_EXP]) return;
    int e = 0;
    while (mt >= g_tileoff[e + 1]) e++;
    int row0 = g_poff[e] + ((mt - g_tileoff[e]) << 7);
    int n0 = blockIdx.y << 7;

    extern __shared__ char smem[];
    __half* sA = reinterpret_cast<__half*>(smem);
    __half* sB = reinterpret_cast<__half*>(smem) + SB_BASE;
    int* s_tok = reinterpret_cast<int*>(smem + TOK_BASE_B);
    uint32_t sbase = smem_u32(smem);

    int tid = threadIdx.x;
    if (tid < 128) s_tok[tid] = g_rows_tok[row0 + tid];
    __syncthreads();

    const __half* wbase = g_w_f16 + (size_t)e * H_DIM * H_DIM + n0;

    auto do_load = [&](int st, int k0) {
        uint32_t aoff = sbase + (uint32_t)(st * SA_ST * 2);
        uint32_t boff = sbase + (uint32_t)((SB_BASE + st * SB_ST) * 2);
#pragma unroll
        for (int ii = 0; ii < 4; ii++) {
            int idx = tid + ii * 256;
            int ra = idx >> 3, ca = idx & 7;
            const char* asrc = (const char*)(g_x_f16 + (size_t)s_tok[ra] * H_DIM + k0) + ca * 16;
            CP_ASYNC16(aoff + (uint32_t)(ra * SA_LD + ca * 8) * 2, asrc);
            int rb = idx >> 4, cb = idx & 15;
            const char* bsrc = (const char*)(wbase + (size_t)(k0 + rb) * H_DIM) + cb * 16;
            CP_ASYNC16(boff + (uint32_t)(rb * SB_LD + cb * 8) * 2, bsrc);
        }
        CP_COMMIT();
    };

    int wid = tid >> 5;
    int wm = wid & 3;
    int wn = wid >> 2;

    wmma::fragment<wmma::accumulator, 16, 16, 16, float> acc[2][4];
#pragma unroll
    for (int f = 0; f < 2; f++)
#pragma unroll
        for (int j = 0; j < 4; j++) wmma::fill_fragment(acc[f][j], 0.0f);

    do_load(0, 0);
    do_load(1, 64);

    int st = 0;
    int ld = 2;
    for (int it = 0; it < 16; it++) {
        if (it == 15) { CP_WAIT(0); } else { CP_WAIT(1); }
        __syncthreads();
        if (it + 2 < 16) do_load(ld, (it + 2) << 6);

        const __half* A0 = sA + st * SA_ST + (wm * 32) * SA_LD;
        const __half* B0 = sB + st * SB_ST + wn * 64;
#pragma unroll
        for (int ks = 0; ks < 4; ks++) {
            wmma::fragment<wmma::matrix_a, 16, 16, 16, __half, wmma::row_major> af[2];
            wmma::load_matrix_sync(af[0], A0 + ks * 16, SA_LD);
            wmma::load_matrix_sync(af[1], A0 + 16 * SA_LD + ks * 16, SA_LD);
#pragma unroll
            for (int j = 0; j < 4; j++) {
                wmma::fragment<wmma::matrix_b, 16, 16, 16, __half, wmma::row_major> bf;
                wmma::load_matrix_sync(bf, B0 + (ks * 16) * SB_LD + j * 16, SB_LD);
                wmma::mma_sync(acc[0][j], af[0], bf, acc[0][j]);
                wmma::mma_sync(acc[1][j], af[1], bf, acc[1][j]);
            }
        }
        st = (st + 1 == N_STAGE) ? 0 : st + 1;
        ld = (ld + 1 == N_STAGE) ? 0 : ld + 1;
    }

    __syncthreads();
    float* sF = reinterpret_cast<float*>(smem);
#pragma unroll
    for (int f = 0; f < 2; f++)
#pragma unroll
        for (int j = 0; j < 4; j++)
            wmma::store_matrix_sync(sF + (size_t)(wm * 32 + f * 16) * SF_LD + wn * 64 + j * 16,
                                    acc[f][j], SF_LD, wmma::mem_row_major);
    __syncthreads();
#pragma unroll
    for (int q = tid; q < 2048; q += 256) {
        int r = q >> 4;
        int c = (q & 15) << 3;
        const float* src = sF + (size_t)r * SF_LD + c;
        float4 f0 = *reinterpret_cast<const float4*>(src);
        float4 f1 = *reinterpret_cast<const float4*>(src + 4);
        uint4 h;
        h.x = h2_u32(__floats2half2_rn(f0.x, f0.y));
        h.y = h2_u32(__floats2half2_rn(f0.z, f0.w));
        h.z = h2_u32(__floats2half2_rn(f1.x, f1.y));
        h.w = h2_u32(__floats2half2_rn(f1.z, f1.w));
        *reinterpret_cast<uint4*>(g_ybuf_h + (size_t)(row0 + r) * H_DIM + n0 + c) = h;
    }
}

// ---------------- combine: 32 halves/thread, MLP=8, fully coalesced; resets counters ----------------
__global__ void combine_kernel(float* __restrict__ out) {
    int gid = blockIdx.x * blockDim.x + threadIdx.x;   // 262144 threads
    if (gid < N_EXP) { g_counts[gid] = 0; g_cursor[gid] = 0; }   // pre-zero for next launch
    int b = gid >> 5;                 // 32 threads per token row
    int t = gid & 31;
    float2 w = *reinterpret_cast<const float2*>(g_tok_w + 2 * b);
    int2 p = *reinterpret_cast<const int2*>(g_pos + 2 * b);
    float w0 = w.x, w1 = w.y;
    const uint4* ra = reinterpret_cast<const uint4*>(g_ybuf_h + (size_t)p.x * H_DIM);
    const uint4* rb = reinterpret_cast<const uint4*>(g_ybuf_h + (size_t)p.y * H_DIM);
    float4* ob = reinterpret_cast<float4*>(out + (size_t)b * H_DIM);

    // 8 independent loads in flight (4 per gathered row), each warp-instr = 512B coalesced
    uint4 ya[4], yb[4];
#pragma unroll
    for (int q = 0; q < 4; q++) ya[q] = ra[q * 32 + t];
#pragma unroll
    for (int q = 0; q < 4; q++) yb[q] = rb[q * 32 + t];

    float2 a, c;
    float4 o;
#define COMB2(au, bu, ox, oy)                                        \
    a = __half22float2(*reinterpret_cast<__half2*>(&(au)));          \
    c = __half22float2(*reinterpret_cast<__half2*>(&(bu)));          \
    ox = w0 * a.x + w1 * c.x; oy = w0 * a.y + w1 * c.y;

#pragma unroll
    for (int q = 0; q < 4; q++) {
        int o4 = (q * 32 + t) * 2;    // each uint4 (8 halves) = 2 float4
        COMB2(ya[q].x, yb[q].x, o.x, o.y); COMB2(ya[q].y, yb[q].y, o.z, o.w);
        ob[o4] = o;
        COMB2(ya[q].z, yb[q].z, o.x, o.y); COMB2(ya[q].w, yb[q].w, o.z, o.w);
        ob[o4 + 1] = o;
    }
#undef COMB2
}

// ---------------- launch ----------------
extern "C" void kernel_launch(void* const* d_in, const int* in_sizes, int n_in,
                              void* d_out, int out_size) {
    const float* x  = (const float*)d_in[0];
    const float* gw = (const float*)d_in[1];
    const float* ew = (const float*)d_in[2];
    float* out = (float*)d_out;

    cudaFuncSetAttribute(gemm_f16_kernel, cudaFuncAttributeMaxDynamicSharedMemorySize, SMEM_TOTAL);

    prep_kernel<<<3072, 256>>>(x, ew, gw);
    scatter_kernel<<<32, 256>>>();
    gemm_f16_kernel<<<dim3(137, 8), 256, SMEM_TOTAL>>>();
    combine_kernel<<<1024, 256>>>(out);
}